// round 7
// baseline (speedup 1.0000x reference)
#include <cuda_runtime.h>
#include <cuda_bf16.h>
#include <math.h>
#include <stdint.h>

// Problem constants (fixed shapes)
#define BATCH 2
#define TLEN  2048
#define EMB   1024
#define HEADS 16
#define HDIM  64
#define MROWS (BATCH * TLEN)   // 4096
#define SCALE 0.125f           // 1/sqrt(64)
#define LN_EPS 1e-5f

// Scratch (device globals — no allocation allowed)
__device__ float g_K[MROWS * EMB];
__device__ float g_Q[MROWS * EMB];
__device__ float g_V[MROWS * EMB];
__device__ float g_A[MROWS * EMB];

__device__ __nv_bfloat16 g_xh[MROWS * EMB];
__device__ __nv_bfloat16 g_xl[MROWS * EMB];
__device__ __nv_bfloat16 g_ah[MROWS * EMB];
__device__ __nv_bfloat16 g_al[MROWS * EMB];
__device__ __nv_bfloat16 g_Wh[4 * EMB * EMB];
__device__ __nv_bfloat16 g_Wl[4 * EMB * EMB];

// ---------------------------------------------------------------------------
// Helpers
// ---------------------------------------------------------------------------
__device__ __forceinline__ uint32_t s2u(const void* p) {
    return (uint32_t)__cvta_generic_to_shared(p);
}

__device__ __forceinline__ void cp_async16(uint32_t saddr, const void* gaddr) {
    asm volatile("cp.async.cg.shared.global [%0], [%1], 16;"
                 :: "r"(saddr), "l"(gaddr) : "memory");
}

__device__ __forceinline__ void ldsm_x4(uint32_t r[4], uint32_t addr) {
    asm volatile("ldmatrix.sync.aligned.m8n8.x4.shared.b16 {%0,%1,%2,%3}, [%4];"
        : "=r"(r[0]), "=r"(r[1]), "=r"(r[2]), "=r"(r[3]) : "r"(addr));
}

__device__ __forceinline__ void mma_bf16(float c[4], const uint32_t a[4],
                                         uint32_t b0, uint32_t b1) {
    asm volatile(
        "mma.sync.aligned.m16n8k16.row.col.f32.bf16.bf16.f32 "
        "{%0,%1,%2,%3}, {%4,%5,%6,%7}, {%8,%9}, {%0,%1,%2,%3};"
        : "+f"(c[0]), "+f"(c[1]), "+f"(c[2]), "+f"(c[3])
        : "r"(a[0]), "r"(a[1]), "r"(a[2]), "r"(a[3]), "r"(b0), "r"(b1));
}

// Fast exp on the FMA/ALU pipes (no MUFU). Valid for x <= ~0 (softmax args);
// clamped at -80 so exponent reassembly never underflows. Rel err ~6e-5.
__device__ __forceinline__ float fexp(float x) {
    x = fmaxf(x, -80.0f);
    float y = x * 1.44269504088896340736f;      // x * log2(e)
    float r = y + 12582912.0f;                  // 1.5*2^23: round-to-nearest int
    float n = r - 12582912.0f;
    float f = y - n;                            // f in [-0.5, 0.5]
    // 2^f, quartic Taylor in ln2
    float p = 0.0096181291f;                    // ln2^4/24
    p = p * f + 0.0555041087f;                  // ln2^3/6
    p = p * f + 0.2402265069f;                  // ln2^2/2
    p = p * f + 0.6931471806f;                  // ln2
    p = p * f + 1.0f;
    int i = __float_as_int(r) - 1262485504;     // 0x4B400000 -> n as int
    float scale = __int_as_float((i + 127) << 23);
    return p * scale;
}

// ---------------------------------------------------------------------------
// Split fp32 -> bf16 hi + bf16 lo (error-compensated pair). 4 elems/thread.
// ---------------------------------------------------------------------------
__global__ void __launch_bounds__(256) split_kernel(
    const float* __restrict__ X, __nv_bfloat16* __restrict__ hi,
    __nv_bfloat16* __restrict__ lo, int n4)
{
    int i = blockIdx.x * blockDim.x + threadIdx.x;
    if (i >= n4) return;
    float4 v = reinterpret_cast<const float4*>(X)[i];
    float f[4] = {v.x, v.y, v.z, v.w};
    union { __nv_bfloat16 b[4]; uint2 u; } H, L;
    #pragma unroll
    for (int j = 0; j < 4; j++) {
        __nv_bfloat16 h = __float2bfloat16(f[j]);
        H.b[j] = h;
        L.b[j] = __float2bfloat16(f[j] - __bfloat162float(h));
    }
    reinterpret_cast<uint2*>(hi)[i] = H.u;
    reinterpret_cast<uint2*>(lo)[i] = L.u;
}

// ---------------------------------------------------------------------------
// Tensor-core NT GEMM, bf16x3 compensated: C = A @ B^T (fp32-equivalent).
// Block tile 128x128x32, 256 threads, warp tile 32x64.
// Double-buffered cp.async pipeline over K.
// ---------------------------------------------------------------------------
#define BM 128
#define BN 128
#define BK 32
#define LDSW 40                     // padded smem row stride (bf16 elements)
#define STG_ELEMS (128 * LDSW)      // one tensor, one stage
#define STAGE_ELEMS (4 * STG_ELEMS) // Ah, Al, Bh, Bl
#define GEMM_SMEM (2 * STAGE_ELEMS * 2)  // bytes = 81920

__global__ void __launch_bounds__(256, 2) gemm_bf16x3_kernel(
    const __nv_bfloat16* __restrict__ Ah, const __nv_bfloat16* __restrict__ Al,
    const __nv_bfloat16* __restrict__ Bh, const __nv_bfloat16* __restrict__ Bl,
    float* __restrict__ C, int M, int N, int K)
{
    extern __shared__ __nv_bfloat16 smem[];

    const int tid  = threadIdx.x;
    const int m0   = blockIdx.y * BM;
    const int n0   = blockIdx.x * BN;
    const int w    = tid >> 5;
    const int lane = tid & 31;
    const int wm   = (w >> 1) * 32;   // warp m-offset
    const int wn   = (w & 1) * 64;    // warp n-offset
    const int arow = lane & 15;
    const int acol = (lane >> 4) * 8;

    float acc[2][8][4];
    #pragma unroll
    for (int mf = 0; mf < 2; mf++)
        #pragma unroll
        for (int nf = 0; nf < 8; nf++)
            #pragma unroll
            for (int r = 0; r < 4; r++) acc[mf][nf][r] = 0.0f;

    const int NK = K / BK;   // 32

    auto load_stage = [&](int kc, int s) {
        const int k0 = kc * BK;
        __nv_bfloat16* base = smem + s * STAGE_ELEMS;
        const uint32_t sb = s2u(base);
        #pragma unroll
        for (int j = 0; j < 2; j++) {
            int u   = tid + j * 256;      // 0..511
            int row = u >> 2;
            int c   = (u & 3) * 8;        // element offset (8 bf16 = 16B)
            uint32_t so = (uint32_t)(row * LDSW + c) * 2;
            size_t ga = (size_t)(m0 + row) * K + k0 + c;
            size_t gb = (size_t)(n0 + row) * K + k0 + c;
            cp_async16(sb + 0 * STG_ELEMS * 2 + so, Ah + ga);
            cp_async16(sb + 1 * STG_ELEMS * 2 + so, Al + ga);
            cp_async16(sb + 2 * STG_ELEMS * 2 + so, Bh + gb);
            cp_async16(sb + 3 * STG_ELEMS * 2 + so, Bl + gb);
        }
        asm volatile("cp.async.commit_group;");
    };

    load_stage(0, 0);

    for (int kc = 0; kc < NK; kc++) {
        if (kc + 1 < NK) {
            load_stage(kc + 1, (kc + 1) & 1);
            asm volatile("cp.async.wait_group 1;" ::: "memory");
        } else {
            asm volatile("cp.async.wait_group 0;" ::: "memory");
        }
        __syncthreads();

        const int s = kc & 1;
        __nv_bfloat16 (*sAh)[LDSW] =
            reinterpret_cast<__nv_bfloat16(*)[LDSW]>(smem + s * STAGE_ELEMS);
        __nv_bfloat16 (*sAl)[LDSW] =
            reinterpret_cast<__nv_bfloat16(*)[LDSW]>(smem + s * STAGE_ELEMS + STG_ELEMS);
        __nv_bfloat16 (*sBh)[LDSW] =
            reinterpret_cast<__nv_bfloat16(*)[LDSW]>(smem + s * STAGE_ELEMS + 2 * STG_ELEMS);
        __nv_bfloat16 (*sBl)[LDSW] =
            reinterpret_cast<__nv_bfloat16(*)[LDSW]>(smem + s * STAGE_ELEMS + 3 * STG_ELEMS);

        #pragma unroll
        for (int kf = 0; kf < 2; kf++) {
            uint32_t a_h[2][4], a_l[2][4];
            #pragma unroll
            for (int mf = 0; mf < 2; mf++) {
                ldsm_x4(a_h[mf], s2u(&sAh[wm + mf * 16 + arow][kf * 16 + acol]));
                ldsm_x4(a_l[mf], s2u(&sAl[wm + mf * 16 + arow][kf * 16 + acol]));
            }
            #pragma unroll
            for (int nb = 0; nb < 4; nb++) {
                uint32_t b_h[4], b_l[4];
                ldsm_x4(b_h, s2u(&sBh[wn + nb * 16 + arow][kf * 16 + acol]));
                ldsm_x4(b_l, s2u(&sBl[wn + nb * 16 + arow][kf * 16 + acol]));
                #pragma unroll
                for (int mf = 0; mf < 2; mf++) {
                    mma_bf16(acc[mf][2 * nb],     a_h[mf], b_h[0], b_h[2]);
                    mma_bf16(acc[mf][2 * nb],     a_h[mf], b_l[0], b_l[2]);
                    mma_bf16(acc[mf][2 * nb],     a_l[mf], b_h[0], b_h[2]);
                    mma_bf16(acc[mf][2 * nb + 1], a_h[mf], b_h[1], b_h[3]);
                    mma_bf16(acc[mf][2 * nb + 1], a_h[mf], b_l[1], b_l[3]);
                    mma_bf16(acc[mf][2 * nb + 1], a_l[mf], b_h[1], b_h[3]);
                }
            }
        }
        __syncthreads();
    }

    #pragma unroll
    for (int mf = 0; mf < 2; mf++) {
        int row = m0 + wm + mf * 16 + (lane >> 2);
        #pragma unroll
        for (int nf = 0; nf < 8; nf++) {
            int col = n0 + wn + nf * 8 + (lane & 3) * 2;
            *reinterpret_cast<float2*>(&C[(size_t)row * N + col]) =
                make_float2(acc[mf][nf][0], acc[mf][nf][1]);
            *reinterpret_cast<float2*>(&C[(size_t)(row + 8) * N + col]) =
                make_float2(acc[mf][nf][2], acc[mf][nf][3]);
        }
    }
}

// ---------------------------------------------------------------------------
// Per-head LayerNorm over last dim (64). One warp per row. In-place.
// ---------------------------------------------------------------------------
__global__ void __launch_bounds__(256) ln_kernel(
    float* __restrict__ X, const float* __restrict__ w,
    const float* __restrict__ bias, int rows)
{
    int warp = (blockIdx.x * blockDim.x + threadIdx.x) >> 5;
    int lane = threadIdx.x & 31;
    if (warp >= rows) return;

    float* r = X + (size_t)warp * HDIM;
    float v0 = r[lane];
    float v1 = r[lane + 32];

    float sum = v0 + v1;
    #pragma unroll
    for (int o = 16; o > 0; o >>= 1) sum += __shfl_xor_sync(0xffffffffu, sum, o);
    float mu = sum * (1.0f / 64.0f);

    float d0 = v0 - mu, d1 = v1 - mu;
    float sq = d0 * d0 + d1 * d1;
    #pragma unroll
    for (int o = 16; o > 0; o >>= 1) sq += __shfl_xor_sync(0xffffffffu, sq, o);
    float inv = rsqrtf(sq * (1.0f / 64.0f) + LN_EPS);

    r[lane]      = d0 * inv * w[lane]      + bias[lane];
    r[lane + 32] = d1 * inv * w[lane + 32] + bias[lane + 32];
}

// ---------------------------------------------------------------------------
// Causal flash attention. One thread per query row, 64 queries per block.
// exp via FMA-pipe fexp (MUFU was the bottleneck: ~67M exps @ rt8/SMSP).
// ---------------------------------------------------------------------------
__global__ void __launch_bounds__(64) attn_kernel(
    const float* __restrict__ Q, const float* __restrict__ K,
    const float* __restrict__ V, float* __restrict__ O)
{
    extern __shared__ float sm[];
    float* Ks  = sm;           // [64][64]
    float* Vs  = sm + 4096;    // [64][64]
    float* Ssc = sm + 8192;    // [64][65]

    const int tid = threadIdx.x;
    const int qb  = blockIdx.x;
    const int h   = blockIdx.y;
    const int b   = blockIdx.z;
    const int q   = qb * 64 + tid;

    const float* Qrow = Q + ((size_t)(b * TLEN + q) * HEADS + h) * HDIM;
    float qr[64];
    #pragma unroll
    for (int k = 0; k < 64; k++) qr[k] = Qrow[k] * SCALE;

    float acc[64];
    #pragma unroll
    for (int k = 0; k < 64; k++) acc[k] = 0.0f;
    float mrun = -INFINITY;
    float lrun = 0.0f;

    float* myS = Ssc + tid * 65;

    for (int j0 = 0; j0 <= qb * 64; j0 += 64) {
        __syncthreads();
        #pragma unroll 4
        for (int i = 0; i < 64; i++) {
            size_t gbase = ((size_t)(b * TLEN + j0 + i) * HEADS + h) * HDIM + tid;
            Ks[i * 64 + tid] = K[gbase];
            Vs[i * 64 + tid] = V[gbase];
        }
        __syncthreads();

        int jmax = q - j0 + 1;
        if (jmax > 64) jmax = 64;

        float tmax = -INFINITY;
        for (int j = 0; j < jmax; j++) {
            const float4* kr = reinterpret_cast<const float4*>(&Ks[j * 64]);
            float s = 0.0f;
            #pragma unroll
            for (int kk = 0; kk < 16; kk++) {
                float4 kv = kr[kk];
                s += qr[4 * kk + 0] * kv.x + qr[4 * kk + 1] * kv.y
                   + qr[4 * kk + 2] * kv.z + qr[4 * kk + 3] * kv.w;
            }
            myS[j] = s;
            if (s > tmax) tmax = s;
        }

        float newm = fmaxf(mrun, tmax);
        float corr = fexp(mrun - newm);
        lrun *= corr;
        #pragma unroll
        for (int k = 0; k < 64; k++) acc[k] *= corr;

        for (int j = 0; j < jmax; j++) {
            float p = fexp(myS[j] - newm);
            lrun += p;
            const float4* vr = reinterpret_cast<const float4*>(&Vs[j * 64]);
            #pragma unroll
            for (int kk = 0; kk < 16; kk++) {
                float4 vv = vr[kk];
                acc[4 * kk + 0] += p * vv.x;
                acc[4 * kk + 1] += p * vv.y;
                acc[4 * kk + 2] += p * vv.z;
                acc[4 * kk + 3] += p * vv.w;
            }
        }
        mrun = newm;
    }

    float inv = 1.0f / lrun;
    float* Orow = O + (size_t)(b * TLEN + q) * EMB + h * HDIM;
    #pragma unroll
    for (int k = 0; k < 64; k++) Orow[k] = acc[k] * inv;
}

// ---------------------------------------------------------------------------
// Launcher
// ---------------------------------------------------------------------------
extern "C" void kernel_launch(void* const* d_in, const int* in_sizes, int n_in,
                              void* d_out, int out_size)
{
    const float* x    = (const float*)d_in[0];
    const float* Wk   = (const float*)d_in[1];
    const float* Wq   = (const float*)d_in[2];
    const float* Wv   = (const float*)d_in[3];
    const float* Wu   = (const float*)d_in[4];
    const float* klnw = (const float*)d_in[5];
    const float* klnb = (const float*)d_in[6];
    const float* qlnw = (const float*)d_in[7];
    const float* qlnb = (const float*)d_in[8];
    float* out = (float*)d_out;

    float *Kp, *Qp, *Vp, *Ap;
    __nv_bfloat16 *xh, *xl, *ah, *al, *Wh, *Wl;
    cudaGetSymbolAddress((void**)&Kp, g_K);
    cudaGetSymbolAddress((void**)&Qp, g_Q);
    cudaGetSymbolAddress((void**)&Vp, g_V);
    cudaGetSymbolAddress((void**)&Ap, g_A);
    cudaGetSymbolAddress((void**)&xh, g_xh);
    cudaGetSymbolAddress((void**)&xl, g_xl);
    cudaGetSymbolAddress((void**)&ah, g_ah);
    cudaGetSymbolAddress((void**)&al, g_al);
    cudaGetSymbolAddress((void**)&Wh, g_Wh);
    cudaGetSymbolAddress((void**)&Wl, g_Wl);

    const int WN = EMB * EMB;

    // Split conversions
    split_kernel<<<(MROWS * EMB / 4 + 255) / 256, 256>>>(x, xh, xl, MROWS * EMB / 4);
    split_kernel<<<(WN / 4 + 255) / 256, 256>>>(Wk, Wh + 0 * WN, Wl + 0 * WN, WN / 4);
    split_kernel<<<(WN / 4 + 255) / 256, 256>>>(Wq, Wh + 1 * WN, Wl + 1 * WN, WN / 4);
    split_kernel<<<(WN / 4 + 255) / 256, 256>>>(Wv, Wh + 2 * WN, Wl + 2 * WN, WN / 4);
    split_kernel<<<(WN / 4 + 255) / 256, 256>>>(Wu, Wh + 3 * WN, Wl + 3 * WN, WN / 4);

    // QKV projections (tensor cores, pipelined)
    cudaFuncSetAttribute(gemm_bf16x3_kernel,
                         cudaFuncAttributeMaxDynamicSharedMemorySize, GEMM_SMEM);
    dim3 ggrid(EMB / BN, MROWS / BM);
    gemm_bf16x3_kernel<<<ggrid, 256, GEMM_SMEM>>>(xh, xl, Wh + 0 * WN, Wl + 0 * WN, Kp, MROWS, EMB, EMB);
    gemm_bf16x3_kernel<<<ggrid, 256, GEMM_SMEM>>>(xh, xl, Wh + 1 * WN, Wl + 1 * WN, Qp, MROWS, EMB, EMB);
    gemm_bf16x3_kernel<<<ggrid, 256, GEMM_SMEM>>>(xh, xl, Wh + 2 * WN, Wl + 2 * WN, Vp, MROWS, EMB, EMB);

    // LayerNorms
    int rows = MROWS * HEADS;
    ln_kernel<<<rows / 8, 256>>>(Kp, klnw, klnb, rows);
    ln_kernel<<<rows / 8, 256>>>(Qp, qlnw, qlnb, rows);

    // Attention
    int smem = (4096 + 4096 + 64 * 65) * (int)sizeof(float);
    cudaFuncSetAttribute(attn_kernel, cudaFuncAttributeMaxDynamicSharedMemorySize, smem);
    dim3 agrid(TLEN / 64, HEADS, BATCH);
    attn_kernel<<<agrid, 64, smem>>>(Qp, Kp, Vp, Ap);

    // Output projection
    split_kernel<<<(MROWS * EMB / 4 + 255) / 256, 256>>>(Ap, ah, al, MROWS * EMB / 4);
    gemm_bf16x3_kernel<<<ggrid, 256, GEMM_SMEM>>>(ah, al, Wh + 3 * WN, Wl + 3 * WN, out, MROWS, EMB, EMB);
}

// round 8
// speedup vs baseline: 1.0256x; 1.0256x over previous
#include <cuda_runtime.h>
#include <cuda_bf16.h>
#include <math.h>
#include <stdint.h>

// Problem constants (fixed shapes)
#define BATCH 2
#define TLEN  2048
#define EMB   1024
#define HEADS 16
#define HDIM  64
#define MROWS (BATCH * TLEN)   // 4096
#define SCALE 0.125f           // 1/sqrt(64)
#define LN_EPS 1e-5f

// Scratch (device globals — no allocation allowed)
__device__ float g_K[MROWS * EMB];
__device__ float g_Q[MROWS * EMB];
__device__ float g_V[MROWS * EMB];
__device__ float g_A[MROWS * EMB];

__device__ __nv_bfloat16 g_xh[MROWS * EMB];
__device__ __nv_bfloat16 g_xl[MROWS * EMB];
__device__ __nv_bfloat16 g_ah[MROWS * EMB];
__device__ __nv_bfloat16 g_al[MROWS * EMB];
__device__ __nv_bfloat16 g_Wh[4 * EMB * EMB];
__device__ __nv_bfloat16 g_Wl[4 * EMB * EMB];

// ---------------------------------------------------------------------------
// Helpers
// ---------------------------------------------------------------------------
__device__ __forceinline__ uint32_t s2u(const void* p) {
    return (uint32_t)__cvta_generic_to_shared(p);
}

__device__ __forceinline__ void cp_async16(uint32_t saddr, const void* gaddr) {
    asm volatile("cp.async.cg.shared.global [%0], [%1], 16;"
                 :: "r"(saddr), "l"(gaddr) : "memory");
}

__device__ __forceinline__ void ldsm_x4(uint32_t r[4], uint32_t addr) {
    asm volatile("ldmatrix.sync.aligned.m8n8.x4.shared.b16 {%0,%1,%2,%3}, [%4];"
        : "=r"(r[0]), "=r"(r[1]), "=r"(r[2]), "=r"(r[3]) : "r"(addr));
}

__device__ __forceinline__ void mma_bf16(float c[4], const uint32_t a[4],
                                         uint32_t b0, uint32_t b1) {
    asm volatile(
        "mma.sync.aligned.m16n8k16.row.col.f32.bf16.bf16.f32 "
        "{%0,%1,%2,%3}, {%4,%5,%6,%7}, {%8,%9}, {%0,%1,%2,%3};"
        : "+f"(c[0]), "+f"(c[1]), "+f"(c[2]), "+f"(c[3])
        : "r"(a[0]), "r"(a[1]), "r"(a[2]), "r"(a[3]), "r"(b0), "r"(b1));
}

// ---------------------------------------------------------------------------
// Split fp32 -> bf16 hi + bf16 lo (error-compensated pair). 4 elems/thread.
// ---------------------------------------------------------------------------
__global__ void __launch_bounds__(256) split_kernel(
    const float* __restrict__ X, __nv_bfloat16* __restrict__ hi,
    __nv_bfloat16* __restrict__ lo, int n4)
{
    int i = blockIdx.x * blockDim.x + threadIdx.x;
    if (i >= n4) return;
    float4 v = reinterpret_cast<const float4*>(X)[i];
    float f[4] = {v.x, v.y, v.z, v.w};
    union { __nv_bfloat16 b[4]; uint2 u; } H, L;
    #pragma unroll
    for (int j = 0; j < 4; j++) {
        __nv_bfloat16 h = __float2bfloat16(f[j]);
        H.b[j] = h;
        L.b[j] = __float2bfloat16(f[j] - __bfloat162float(h));
    }
    reinterpret_cast<uint2*>(hi)[i] = H.u;
    reinterpret_cast<uint2*>(lo)[i] = L.u;
}

// ---------------------------------------------------------------------------
// Tensor-core NT GEMM, bf16x3 compensated: C = A @ B^T (fp32-equivalent).
// Block tile 128x128x32, 256 threads, warp tile 32x64.
// Double-buffered cp.async pipeline over K.
// ---------------------------------------------------------------------------
#define BM 128
#define BN 128
#define BK 32
#define LDSW 40                     // padded smem row stride (bf16 elements)
#define STG_ELEMS (128 * LDSW)      // one tensor, one stage
#define STAGE_ELEMS (4 * STG_ELEMS) // Ah, Al, Bh, Bl
#define GEMM_SMEM (2 * STAGE_ELEMS * 2)  // bytes = 81920

__global__ void __launch_bounds__(256, 2) gemm_bf16x3_kernel(
    const __nv_bfloat16* __restrict__ Ah, const __nv_bfloat16* __restrict__ Al,
    const __nv_bfloat16* __restrict__ Bh, const __nv_bfloat16* __restrict__ Bl,
    float* __restrict__ C, int M, int N, int K)
{
    extern __shared__ __nv_bfloat16 smem[];

    const int tid  = threadIdx.x;
    const int m0   = blockIdx.y * BM;
    const int n0   = blockIdx.x * BN;
    const int w    = tid >> 5;
    const int lane = tid & 31;
    const int wm   = (w >> 1) * 32;   // warp m-offset
    const int wn   = (w & 1) * 64;    // warp n-offset
    const int arow = lane & 15;
    const int acol = (lane >> 4) * 8;

    float acc[2][8][4];
    #pragma unroll
    for (int mf = 0; mf < 2; mf++)
        #pragma unroll
        for (int nf = 0; nf < 8; nf++)
            #pragma unroll
            for (int r = 0; r < 4; r++) acc[mf][nf][r] = 0.0f;

    const int NK = K / BK;   // 32

    auto load_stage = [&](int kc, int s) {
        const int k0 = kc * BK;
        __nv_bfloat16* base = smem + s * STAGE_ELEMS;
        const uint32_t sb = s2u(base);
        #pragma unroll
        for (int j = 0; j < 2; j++) {
            int u   = tid + j * 256;      // 0..511
            int row = u >> 2;
            int c   = (u & 3) * 8;        // element offset (8 bf16 = 16B)
            uint32_t so = (uint32_t)(row * LDSW + c) * 2;
            size_t ga = (size_t)(m0 + row) * K + k0 + c;
            size_t gb = (size_t)(n0 + row) * K + k0 + c;
            cp_async16(sb + 0 * STG_ELEMS * 2 + so, Ah + ga);
            cp_async16(sb + 1 * STG_ELEMS * 2 + so, Al + ga);
            cp_async16(sb + 2 * STG_ELEMS * 2 + so, Bh + gb);
            cp_async16(sb + 3 * STG_ELEMS * 2 + so, Bl + gb);
        }
        asm volatile("cp.async.commit_group;");
    };

    load_stage(0, 0);

    for (int kc = 0; kc < NK; kc++) {
        if (kc + 1 < NK) {
            load_stage(kc + 1, (kc + 1) & 1);
            asm volatile("cp.async.wait_group 1;" ::: "memory");
        } else {
            asm volatile("cp.async.wait_group 0;" ::: "memory");
        }
        __syncthreads();

        const int s = kc & 1;
        __nv_bfloat16 (*sAh)[LDSW] =
            reinterpret_cast<__nv_bfloat16(*)[LDSW]>(smem + s * STAGE_ELEMS);
        __nv_bfloat16 (*sAl)[LDSW] =
            reinterpret_cast<__nv_bfloat16(*)[LDSW]>(smem + s * STAGE_ELEMS + STG_ELEMS);
        __nv_bfloat16 (*sBh)[LDSW] =
            reinterpret_cast<__nv_bfloat16(*)[LDSW]>(smem + s * STAGE_ELEMS + 2 * STG_ELEMS);
        __nv_bfloat16 (*sBl)[LDSW] =
            reinterpret_cast<__nv_bfloat16(*)[LDSW]>(smem + s * STAGE_ELEMS + 3 * STG_ELEMS);

        #pragma unroll
        for (int kf = 0; kf < 2; kf++) {
            uint32_t a_h[2][4], a_l[2][4];
            #pragma unroll
            for (int mf = 0; mf < 2; mf++) {
                ldsm_x4(a_h[mf], s2u(&sAh[wm + mf * 16 + arow][kf * 16 + acol]));
                ldsm_x4(a_l[mf], s2u(&sAl[wm + mf * 16 + arow][kf * 16 + acol]));
            }
            #pragma unroll
            for (int nb = 0; nb < 4; nb++) {
                uint32_t b_h[4], b_l[4];
                ldsm_x4(b_h, s2u(&sBh[wn + nb * 16 + arow][kf * 16 + acol]));
                ldsm_x4(b_l, s2u(&sBl[wn + nb * 16 + arow][kf * 16 + acol]));
                #pragma unroll
                for (int mf = 0; mf < 2; mf++) {
                    mma_bf16(acc[mf][2 * nb],     a_h[mf], b_h[0], b_h[2]);
                    mma_bf16(acc[mf][2 * nb],     a_h[mf], b_l[0], b_l[2]);
                    mma_bf16(acc[mf][2 * nb],     a_l[mf], b_h[0], b_h[2]);
                    mma_bf16(acc[mf][2 * nb + 1], a_h[mf], b_h[1], b_h[3]);
                    mma_bf16(acc[mf][2 * nb + 1], a_h[mf], b_l[1], b_l[3]);
                    mma_bf16(acc[mf][2 * nb + 1], a_l[mf], b_h[1], b_h[3]);
                }
            }
        }
        __syncthreads();
    }

    #pragma unroll
    for (int mf = 0; mf < 2; mf++) {
        int row = m0 + wm + mf * 16 + (lane >> 2);
        #pragma unroll
        for (int nf = 0; nf < 8; nf++) {
            int col = n0 + wn + nf * 8 + (lane & 3) * 2;
            *reinterpret_cast<float2*>(&C[(size_t)row * N + col]) =
                make_float2(acc[mf][nf][0], acc[mf][nf][1]);
            *reinterpret_cast<float2*>(&C[(size_t)(row + 8) * N + col]) =
                make_float2(acc[mf][nf][2], acc[mf][nf][3]);
        }
    }
}

// ---------------------------------------------------------------------------
// Per-head LayerNorm over last dim (64). One warp per row. In-place.
// ---------------------------------------------------------------------------
__global__ void __launch_bounds__(256) ln_kernel(
    float* __restrict__ X, const float* __restrict__ w,
    const float* __restrict__ bias, int rows)
{
    int warp = (blockIdx.x * blockDim.x + threadIdx.x) >> 5;
    int lane = threadIdx.x & 31;
    if (warp >= rows) return;

    float* r = X + (size_t)warp * HDIM;
    float v0 = r[lane];
    float v1 = r[lane + 32];

    float sum = v0 + v1;
    #pragma unroll
    for (int o = 16; o > 0; o >>= 1) sum += __shfl_xor_sync(0xffffffffu, sum, o);
    float mu = sum * (1.0f / 64.0f);

    float d0 = v0 - mu, d1 = v1 - mu;
    float sq = d0 * d0 + d1 * d1;
    #pragma unroll
    for (int o = 16; o > 0; o >>= 1) sq += __shfl_xor_sync(0xffffffffu, sq, o);
    float inv = rsqrtf(sq * (1.0f / 64.0f) + LN_EPS);

    r[lane]      = d0 * inv * w[lane]      + bias[lane];
    r[lane + 32] = d1 * inv * w[lane + 32] + bias[lane + 32];
}

// ---------------------------------------------------------------------------
// Causal flash attention. One thread per query row, 64 queries per block.
// Pass-1 processes 4 keys/iter with 2 partial sums each: 8 independent FFMA
// chains per thread (the serial 64-FMA chain was the real bottleneck).
// ---------------------------------------------------------------------------
#define SSTRIDE 68   // padded score-row stride (allows 4-wide overrun to 66)

__global__ void __launch_bounds__(64) attn_kernel(
    const float* __restrict__ Q, const float* __restrict__ K,
    const float* __restrict__ V, float* __restrict__ O)
{
    extern __shared__ float sm[];
    float* Ks  = sm;           // [64][64]
    float* Vs  = sm + 4096;    // [64][64]
    float* Ssc = sm + 8192;    // [64][SSTRIDE]

    const int tid = threadIdx.x;
    const int qb  = blockIdx.x;
    const int h   = blockIdx.y;
    const int b   = blockIdx.z;
    const int q   = qb * 64 + tid;

    const float* Qrow = Q + ((size_t)(b * TLEN + q) * HEADS + h) * HDIM;
    float qr[64];
    #pragma unroll
    for (int k = 0; k < 64; k++) qr[k] = Qrow[k] * SCALE;

    float acc[64];
    #pragma unroll
    for (int k = 0; k < 64; k++) acc[k] = 0.0f;
    float mrun = -INFINITY;
    float lrun = 0.0f;

    float* myS = Ssc + tid * SSTRIDE;

    for (int j0 = 0; j0 <= qb * 64; j0 += 64) {
        __syncthreads();
        #pragma unroll 4
        for (int i = 0; i < 64; i++) {
            size_t gbase = ((size_t)(b * TLEN + j0 + i) * HEADS + h) * HDIM + tid;
            Ks[i * 64 + tid] = K[gbase];
            Vs[i * 64 + tid] = V[gbase];
        }
        __syncthreads();

        int jmax = q - j0 + 1;          // 1..64 (last tile) or >=64 (full)
        if (jmax > 64) jmax = 64;

        // pass 1: 4 keys per iteration, 2 partial sums each -> 8 indep chains
        float tmax = -INFINITY;
        for (int j = 0; j < jmax; j += 4) {
            const float4* k0r = reinterpret_cast<const float4*>(&Ks[(j + 0) * 64]);
            const float4* k1r = reinterpret_cast<const float4*>(&Ks[(j + 1) * 64]);
            const float4* k2r = reinterpret_cast<const float4*>(&Ks[(j + 2) * 64]);
            const float4* k3r = reinterpret_cast<const float4*>(&Ks[(j + 3) * 64]);
            float s0a = 0.f, s0b = 0.f, s1a = 0.f, s1b = 0.f;
            float s2a = 0.f, s2b = 0.f, s3a = 0.f, s3b = 0.f;
            #pragma unroll
            for (int kk = 0; kk < 16; kk++) {
                float4 q4 = *reinterpret_cast<const float4*>(&qr[4 * kk]);
                float4 k0v = k0r[kk], k1v = k1r[kk], k2v = k2r[kk], k3v = k3r[kk];
                s0a += q4.x * k0v.x + q4.y * k0v.y;
                s0b += q4.z * k0v.z + q4.w * k0v.w;
                s1a += q4.x * k1v.x + q4.y * k1v.y;
                s1b += q4.z * k1v.z + q4.w * k1v.w;
                s2a += q4.x * k2v.x + q4.y * k2v.y;
                s2b += q4.z * k2v.z + q4.w * k2v.w;
                s3a += q4.x * k3v.x + q4.y * k3v.y;
                s3b += q4.z * k3v.z + q4.w * k3v.w;
            }
            float s0 = (j + 0 < jmax) ? s0a + s0b : -1e30f;
            float s1 = (j + 1 < jmax) ? s1a + s1b : -1e30f;
            float s2 = (j + 2 < jmax) ? s2a + s2b : -1e30f;
            float s3 = (j + 3 < jmax) ? s3a + s3b : -1e30f;
            myS[j + 0] = s0; myS[j + 1] = s1;
            myS[j + 2] = s2; myS[j + 3] = s3;
            tmax = fmaxf(tmax, fmaxf(fmaxf(s0, s1), fmaxf(s2, s3)));
        }

        float newm = fmaxf(mrun, tmax);
        float corr = __expf(mrun - newm);   // 0 when mrun == -inf
        lrun *= corr;
        #pragma unroll
        for (int k = 0; k < 64; k++) acc[k] *= corr;

        // pass 2: accumulate p * V (64 indep FMAs per j; exp on MUFU)
        for (int j = 0; j < jmax; j++) {
            float p = __expf(myS[j] - newm);
            lrun += p;
            const float4* vr = reinterpret_cast<const float4*>(&Vs[j * 64]);
            #pragma unroll
            for (int kk = 0; kk < 16; kk++) {
                float4 vv = vr[kk];
                acc[4 * kk + 0] += p * vv.x;
                acc[4 * kk + 1] += p * vv.y;
                acc[4 * kk + 2] += p * vv.z;
                acc[4 * kk + 3] += p * vv.w;
            }
        }
        mrun = newm;
    }

    float inv = 1.0f / lrun;
    float* Orow = O + (size_t)(b * TLEN + q) * EMB + h * HDIM;
    #pragma unroll
    for (int k = 0; k < 64; k++) Orow[k] = acc[k] * inv;
}

// ---------------------------------------------------------------------------
// Launcher
// ---------------------------------------------------------------------------
extern "C" void kernel_launch(void* const* d_in, const int* in_sizes, int n_in,
                              void* d_out, int out_size)
{
    const float* x    = (const float*)d_in[0];
    const float* Wk   = (const float*)d_in[1];
    const float* Wq   = (const float*)d_in[2];
    const float* Wv   = (const float*)d_in[3];
    const float* Wu   = (const float*)d_in[4];
    const float* klnw = (const float*)d_in[5];
    const float* klnb = (const float*)d_in[6];
    const float* qlnw = (const float*)d_in[7];
    const float* qlnb = (const float*)d_in[8];
    float* out = (float*)d_out;

    float *Kp, *Qp, *Vp, *Ap;
    __nv_bfloat16 *xh, *xl, *ah, *al, *Wh, *Wl;
    cudaGetSymbolAddress((void**)&Kp, g_K);
    cudaGetSymbolAddress((void**)&Qp, g_Q);
    cudaGetSymbolAddress((void**)&Vp, g_V);
    cudaGetSymbolAddress((void**)&Ap, g_A);
    cudaGetSymbolAddress((void**)&xh, g_xh);
    cudaGetSymbolAddress((void**)&xl, g_xl);
    cudaGetSymbolAddress((void**)&ah, g_ah);
    cudaGetSymbolAddress((void**)&al, g_al);
    cudaGetSymbolAddress((void**)&Wh, g_Wh);
    cudaGetSymbolAddress((void**)&Wl, g_Wl);

    const int WN = EMB * EMB;

    // Split conversions
    split_kernel<<<(MROWS * EMB / 4 + 255) / 256, 256>>>(x, xh, xl, MROWS * EMB / 4);
    split_kernel<<<(WN / 4 + 255) / 256, 256>>>(Wk, Wh + 0 * WN, Wl + 0 * WN, WN / 4);
    split_kernel<<<(WN / 4 + 255) / 256, 256>>>(Wq, Wh + 1 * WN, Wl + 1 * WN, WN / 4);
    split_kernel<<<(WN / 4 + 255) / 256, 256>>>(Wv, Wh + 2 * WN, Wl + 2 * WN, WN / 4);
    split_kernel<<<(WN / 4 + 255) / 256, 256>>>(Wu, Wh + 3 * WN, Wl + 3 * WN, WN / 4);

    // QKV projections (tensor cores, pipelined)
    cudaFuncSetAttribute(gemm_bf16x3_kernel,
                         cudaFuncAttributeMaxDynamicSharedMemorySize, GEMM_SMEM);
    dim3 ggrid(EMB / BN, MROWS / BM);
    gemm_bf16x3_kernel<<<ggrid, 256, GEMM_SMEM>>>(xh, xl, Wh + 0 * WN, Wl + 0 * WN, Kp, MROWS, EMB, EMB);
    gemm_bf16x3_kernel<<<ggrid, 256, GEMM_SMEM>>>(xh, xl, Wh + 1 * WN, Wl + 1 * WN, Qp, MROWS, EMB, EMB);
    gemm_bf16x3_kernel<<<ggrid, 256, GEMM_SMEM>>>(xh, xl, Wh + 2 * WN, Wl + 2 * WN, Vp, MROWS, EMB, EMB);

    // LayerNorms
    int rows = MROWS * HEADS;
    ln_kernel<<<rows / 8, 256>>>(Kp, klnw, klnb, rows);
    ln_kernel<<<rows / 8, 256>>>(Qp, qlnw, qlnb, rows);

    // Attention
    int smem = (4096 + 4096 + 64 * SSTRIDE) * (int)sizeof(float);
    cudaFuncSetAttribute(attn_kernel, cudaFuncAttributeMaxDynamicSharedMemorySize, smem);
    dim3 agrid(TLEN / 64, HEADS, BATCH);
    attn_kernel<<<agrid, 64, smem>>>(Qp, Kp, Vp, Ap);

    // Output projection
    split_kernel<<<(MROWS * EMB / 4 + 255) / 256, 256>>>(Ap, ah, al, MROWS * EMB / 4);
    gemm_bf16x3_kernel<<<ggrid, 256, GEMM_SMEM>>>(ah, al, Wh + 3 * WN, Wl + 3 * WN, out, MROWS, EMB, EMB);
}

// round 9
// speedup vs baseline: 1.1992x; 1.1693x over previous
#include <cuda_runtime.h>
#include <cuda_fp16.h>
#include <math.h>
#include <stdint.h>

// Problem constants (fixed shapes)
#define BATCH 2
#define TLEN  2048
#define EMB   1024
#define HEADS 16
#define HDIM  64
#define MROWS (BATCH * TLEN)   // 4096
#define SCALE 0.125f           // 1/sqrt(64)
#define LN_EPS 1e-5f

// Scratch (device globals — no allocation allowed)
__device__ float g_K[MROWS * EMB];
__device__ float g_Q[MROWS * EMB];
__device__ float g_V[MROWS * EMB];
__device__ float g_A[MROWS * EMB];

__device__ __half g_xf[MROWS * EMB];
__device__ __half g_af[MROWS * EMB];
__device__ __half g_Wf[4 * EMB * EMB];

// ---------------------------------------------------------------------------
// Helpers
// ---------------------------------------------------------------------------
__device__ __forceinline__ uint32_t s2u(const void* p) {
    return (uint32_t)__cvta_generic_to_shared(p);
}

__device__ __forceinline__ void cp_async16(uint32_t saddr, const void* gaddr) {
    asm volatile("cp.async.cg.shared.global [%0], [%1], 16;"
                 :: "r"(saddr), "l"(gaddr) : "memory");
}

__device__ __forceinline__ void ldsm_x4(uint32_t r[4], uint32_t addr) {
    asm volatile("ldmatrix.sync.aligned.m8n8.x4.shared.b16 {%0,%1,%2,%3}, [%4];"
        : "=r"(r[0]), "=r"(r[1]), "=r"(r[2]), "=r"(r[3]) : "r"(addr));
}

__device__ __forceinline__ void mma_fp16(float c[4], const uint32_t a[4],
                                         uint32_t b0, uint32_t b1) {
    asm volatile(
        "mma.sync.aligned.m16n8k16.row.col.f32.f16.f16.f32 "
        "{%0,%1,%2,%3}, {%4,%5,%6,%7}, {%8,%9}, {%0,%1,%2,%3};"
        : "+f"(c[0]), "+f"(c[1]), "+f"(c[2]), "+f"(c[3])
        : "r"(a[0]), "r"(a[1]), "r"(a[2]), "r"(a[3]), "r"(b0), "r"(b1));
}

// ---------------------------------------------------------------------------
// Convert fp32 -> fp16. 4 elems/thread.
// ---------------------------------------------------------------------------
__global__ void __launch_bounds__(256) cvt_kernel(
    const float* __restrict__ X, __half* __restrict__ Y, int n4)
{
    int i = blockIdx.x * blockDim.x + threadIdx.x;
    if (i >= n4) return;
    float4 v = reinterpret_cast<const float4*>(X)[i];
    union { __half h[4]; uint2 u; } H;
    H.h[0] = __float2half(v.x);
    H.h[1] = __float2half(v.y);
    H.h[2] = __float2half(v.z);
    H.h[3] = __float2half(v.w);
    reinterpret_cast<uint2*>(Y)[i] = H.u;
}

// ---------------------------------------------------------------------------
// Tensor-core NT GEMM, single-pass fp16, fp32 accum: C = A @ B^T.
// Block tile 128x128x32, 256 threads, warp tile 32x64.
// Double-buffered cp.async pipeline over K.
// ---------------------------------------------------------------------------
#define BM 128
#define BN 128
#define BK 32
#define LDSW 40                      // padded smem row stride (half elements)
#define STG_ELEMS (128 * LDSW)       // one tensor, one stage
#define STAGE_ELEMS (2 * STG_ELEMS)  // A, B
#define GEMM_SMEM (2 * STAGE_ELEMS * 2)   // bytes = 40960

__global__ void __launch_bounds__(256, 2) gemm_fp16_kernel(
    const __half* __restrict__ A, const __half* __restrict__ B,
    float* __restrict__ C, int M, int N, int K)
{
    extern __shared__ __half smem[];

    const int tid  = threadIdx.x;
    const int m0   = blockIdx.y * BM;
    const int n0   = blockIdx.x * BN;
    const int w    = tid >> 5;
    const int lane = tid & 31;
    const int wm   = (w >> 1) * 32;   // warp m-offset
    const int wn   = (w & 1) * 64;    // warp n-offset
    const int arow = lane & 15;
    const int acol = (lane >> 4) * 8;

    float acc[2][8][4];
    #pragma unroll
    for (int mf = 0; mf < 2; mf++)
        #pragma unroll
        for (int nf = 0; nf < 8; nf++)
            #pragma unroll
            for (int r = 0; r < 4; r++) acc[mf][nf][r] = 0.0f;

    const int NK = K / BK;   // 32

    auto load_stage = [&](int kc, int s) {
        const int k0 = kc * BK;
        __half* base = smem + s * STAGE_ELEMS;
        const uint32_t sb = s2u(base);
        #pragma unroll
        for (int j = 0; j < 2; j++) {
            int u   = tid + j * 256;      // 0..511
            int row = u >> 2;
            int c   = (u & 3) * 8;        // element offset (8 half = 16B)
            uint32_t so = (uint32_t)(row * LDSW + c) * 2;
            size_t ga = (size_t)(m0 + row) * K + k0 + c;
            size_t gb = (size_t)(n0 + row) * K + k0 + c;
            cp_async16(sb + 0 * STG_ELEMS * 2 + so, A + ga);
            cp_async16(sb + 1 * STG_ELEMS * 2 + so, B + gb);
        }
        asm volatile("cp.async.commit_group;");
    };

    load_stage(0, 0);

    for (int kc = 0; kc < NK; kc++) {
        if (kc + 1 < NK) {
            load_stage(kc + 1, (kc + 1) & 1);
            asm volatile("cp.async.wait_group 1;" ::: "memory");
        } else {
            asm volatile("cp.async.wait_group 0;" ::: "memory");
        }
        __syncthreads();

        const int s = kc & 1;
        __half (*sA)[LDSW] =
            reinterpret_cast<__half(*)[LDSW]>(smem + s * STAGE_ELEMS);
        __half (*sB)[LDSW] =
            reinterpret_cast<__half(*)[LDSW]>(smem + s * STAGE_ELEMS + STG_ELEMS);

        #pragma unroll
        for (int kf = 0; kf < 2; kf++) {
            uint32_t af[2][4];
            #pragma unroll
            for (int mf = 0; mf < 2; mf++)
                ldsm_x4(af[mf], s2u(&sA[wm + mf * 16 + arow][kf * 16 + acol]));
            #pragma unroll
            for (int nb = 0; nb < 4; nb++) {
                uint32_t bf[4];
                ldsm_x4(bf, s2u(&sB[wn + nb * 16 + arow][kf * 16 + acol]));
                #pragma unroll
                for (int mf = 0; mf < 2; mf++) {
                    mma_fp16(acc[mf][2 * nb],     af[mf], bf[0], bf[2]);
                    mma_fp16(acc[mf][2 * nb + 1], af[mf], bf[1], bf[3]);
                }
            }
        }
        __syncthreads();
    }

    #pragma unroll
    for (int mf = 0; mf < 2; mf++) {
        int row = m0 + wm + mf * 16 + (lane >> 2);
        #pragma unroll
        for (int nf = 0; nf < 8; nf++) {
            int col = n0 + wn + nf * 8 + (lane & 3) * 2;
            *reinterpret_cast<float2*>(&C[(size_t)row * N + col]) =
                make_float2(acc[mf][nf][0], acc[mf][nf][1]);
            *reinterpret_cast<float2*>(&C[(size_t)(row + 8) * N + col]) =
                make_float2(acc[mf][nf][2], acc[mf][nf][3]);
        }
    }
}

// ---------------------------------------------------------------------------
// Per-head LayerNorm over last dim (64). One warp per row. In-place.
// ---------------------------------------------------------------------------
__global__ void __launch_bounds__(256) ln_kernel(
    float* __restrict__ X, const float* __restrict__ w,
    const float* __restrict__ bias, int rows)
{
    int warp = (blockIdx.x * blockDim.x + threadIdx.x) >> 5;
    int lane = threadIdx.x & 31;
    if (warp >= rows) return;

    float* r = X + (size_t)warp * HDIM;
    float v0 = r[lane];
    float v1 = r[lane + 32];

    float sum = v0 + v1;
    #pragma unroll
    for (int o = 16; o > 0; o >>= 1) sum += __shfl_xor_sync(0xffffffffu, sum, o);
    float mu = sum * (1.0f / 64.0f);

    float d0 = v0 - mu, d1 = v1 - mu;
    float sq = d0 * d0 + d1 * d1;
    #pragma unroll
    for (int o = 16; o > 0; o >>= 1) sq += __shfl_xor_sync(0xffffffffu, sq, o);
    float inv = rsqrtf(sq * (1.0f / 64.0f) + LN_EPS);

    r[lane]      = d0 * inv * w[lane]      + bias[lane];
    r[lane + 32] = d1 * inv * w[lane + 32] + bias[lane + 32];
}

// ---------------------------------------------------------------------------
// Causal flash attention. One thread per query row, 64 queries per block.
// Pass-1: 4 keys/iter, 2 partial sums each (8 independent FFMA chains).
// ---------------------------------------------------------------------------
#define SSTRIDE 68   // padded score-row stride (allows 4-wide overrun to 66)

__global__ void __launch_bounds__(64) attn_kernel(
    const float* __restrict__ Q, const float* __restrict__ K,
    const float* __restrict__ V, float* __restrict__ O)
{
    extern __shared__ float sm[];
    float* Ks  = sm;           // [64][64]
    float* Vs  = sm + 4096;    // [64][64]
    float* Ssc = sm + 8192;    // [64][SSTRIDE]

    const int tid = threadIdx.x;
    const int qb  = blockIdx.x;
    const int h   = blockIdx.y;
    const int b   = blockIdx.z;
    const int q   = qb * 64 + tid;

    const float* Qrow = Q + ((size_t)(b * TLEN + q) * HEADS + h) * HDIM;
    float qr[64];
    #pragma unroll
    for (int k = 0; k < 64; k++) qr[k] = Qrow[k] * SCALE;

    float acc[64];
    #pragma unroll
    for (int k = 0; k < 64; k++) acc[k] = 0.0f;
    float mrun = -INFINITY;
    float lrun = 0.0f;

    float* myS = Ssc + tid * SSTRIDE;

    for (int j0 = 0; j0 <= qb * 64; j0 += 64) {
        __syncthreads();
        #pragma unroll 4
        for (int i = 0; i < 64; i++) {
            size_t gbase = ((size_t)(b * TLEN + j0 + i) * HEADS + h) * HDIM + tid;
            Ks[i * 64 + tid] = K[gbase];
            Vs[i * 64 + tid] = V[gbase];
        }
        __syncthreads();

        int jmax = q - j0 + 1;
        if (jmax > 64) jmax = 64;

        float tmax = -INFINITY;
        for (int j = 0; j < jmax; j += 4) {
            const float4* k0r = reinterpret_cast<const float4*>(&Ks[(j + 0) * 64]);
            const float4* k1r = reinterpret_cast<const float4*>(&Ks[(j + 1) * 64]);
            const float4* k2r = reinterpret_cast<const float4*>(&Ks[(j + 2) * 64]);
            const float4* k3r = reinterpret_cast<const float4*>(&Ks[(j + 3) * 64]);
            float s0a = 0.f, s0b = 0.f, s1a = 0.f, s1b = 0.f;
            float s2a = 0.f, s2b = 0.f, s3a = 0.f, s3b = 0.f;
            #pragma unroll
            for (int kk = 0; kk < 16; kk++) {
                float4 q4 = *reinterpret_cast<const float4*>(&qr[4 * kk]);
                float4 k0v = k0r[kk], k1v = k1r[kk], k2v = k2r[kk], k3v = k3r[kk];
                s0a += q4.x * k0v.x + q4.y * k0v.y;
                s0b += q4.z * k0v.z + q4.w * k0v.w;
                s1a += q4.x * k1v.x + q4.y * k1v.y;
                s1b += q4.z * k1v.z + q4.w * k1v.w;
                s2a += q4.x * k2v.x + q4.y * k2v.y;
                s2b += q4.z * k2v.z + q4.w * k2v.w;
                s3a += q4.x * k3v.x + q4.y * k3v.y;
                s3b += q4.z * k3v.z + q4.w * k3v.w;
            }
            float s0 = (j + 0 < jmax) ? s0a + s0b : -1e30f;
            float s1 = (j + 1 < jmax) ? s1a + s1b : -1e30f;
            float s2 = (j + 2 < jmax) ? s2a + s2b : -1e30f;
            float s3 = (j + 3 < jmax) ? s3a + s3b : -1e30f;
            myS[j + 0] = s0; myS[j + 1] = s1;
            myS[j + 2] = s2; myS[j + 3] = s3;
            tmax = fmaxf(tmax, fmaxf(fmaxf(s0, s1), fmaxf(s2, s3)));
        }

        float newm = fmaxf(mrun, tmax);
        float corr = __expf(mrun - newm);
        lrun *= corr;
        #pragma unroll
        for (int k = 0; k < 64; k++) acc[k] *= corr;

        for (int j = 0; j < jmax; j++) {
            float p = __expf(myS[j] - newm);
            lrun += p;
            const float4* vr = reinterpret_cast<const float4*>(&Vs[j * 64]);
            #pragma unroll
            for (int kk = 0; kk < 16; kk++) {
                float4 vv = vr[kk];
                acc[4 * kk + 0] += p * vv.x;
                acc[4 * kk + 1] += p * vv.y;
                acc[4 * kk + 2] += p * vv.z;
                acc[4 * kk + 3] += p * vv.w;
            }
        }
        mrun = newm;
    }

    float inv = 1.0f / lrun;
    float* Orow = O + (size_t)(b * TLEN + q) * EMB + h * HDIM;
    #pragma unroll
    for (int k = 0; k < 64; k++) Orow[k] = acc[k] * inv;
}

// ---------------------------------------------------------------------------
// Launcher
// ---------------------------------------------------------------------------
extern "C" void kernel_launch(void* const* d_in, const int* in_sizes, int n_in,
                              void* d_out, int out_size)
{
    const float* x    = (const float*)d_in[0];
    const float* Wk   = (const float*)d_in[1];
    const float* Wq   = (const float*)d_in[2];
    const float* Wv   = (const float*)d_in[3];
    const float* Wu   = (const float*)d_in[4];
    const float* klnw = (const float*)d_in[5];
    const float* klnb = (const float*)d_in[6];
    const float* qlnw = (const float*)d_in[7];
    const float* qlnb = (const float*)d_in[8];
    float* out = (float*)d_out;

    float *Kp, *Qp, *Vp, *Ap;
    __half *xf, *af, *Wf;
    cudaGetSymbolAddress((void**)&Kp, g_K);
    cudaGetSymbolAddress((void**)&Qp, g_Q);
    cudaGetSymbolAddress((void**)&Vp, g_V);
    cudaGetSymbolAddress((void**)&Ap, g_A);
    cudaGetSymbolAddress((void**)&xf, g_xf);
    cudaGetSymbolAddress((void**)&af, g_af);
    cudaGetSymbolAddress((void**)&Wf, g_Wf);

    const int WN = EMB * EMB;

    // Conversions to fp16
    cvt_kernel<<<(MROWS * EMB / 4 + 255) / 256, 256>>>(x, xf, MROWS * EMB / 4);
    cvt_kernel<<<(WN / 4 + 255) / 256, 256>>>(Wk, Wf + 0 * WN, WN / 4);
    cvt_kernel<<<(WN / 4 + 255) / 256, 256>>>(Wq, Wf + 1 * WN, WN / 4);
    cvt_kernel<<<(WN / 4 + 255) / 256, 256>>>(Wv, Wf + 2 * WN, WN / 4);
    cvt_kernel<<<(WN / 4 + 255) / 256, 256>>>(Wu, Wf + 3 * WN, WN / 4);

    // QKV projections (tensor cores, single-pass fp16)
    cudaFuncSetAttribute(gemm_fp16_kernel,
                         cudaFuncAttributeMaxDynamicSharedMemorySize, GEMM_SMEM);
    dim3 ggrid(EMB / BN, MROWS / BM);
    gemm_fp16_kernel<<<ggrid, 256, GEMM_SMEM>>>(xf, Wf + 0 * WN, Kp, MROWS, EMB, EMB);
    gemm_fp16_kernel<<<ggrid, 256, GEMM_SMEM>>>(xf, Wf + 1 * WN, Qp, MROWS, EMB, EMB);
    gemm_fp16_kernel<<<ggrid, 256, GEMM_SMEM>>>(xf, Wf + 2 * WN, Vp, MROWS, EMB, EMB);

    // LayerNorms
    int rows = MROWS * HEADS;
    ln_kernel<<<rows / 8, 256>>>(Kp, klnw, klnb, rows);
    ln_kernel<<<rows / 8, 256>>>(Qp, qlnw, qlnb, rows);

    // Attention
    int smem = (4096 + 4096 + 64 * SSTRIDE) * (int)sizeof(float);
    cudaFuncSetAttribute(attn_kernel, cudaFuncAttributeMaxDynamicSharedMemorySize, smem);
    dim3 agrid(TLEN / 64, HEADS, BATCH);
    attn_kernel<<<agrid, 64, smem>>>(Qp, Kp, Vp, Ap);

    // Output projection
    cvt_kernel<<<(MROWS * EMB / 4 + 255) / 256, 256>>>(Ap, af, MROWS * EMB / 4);
    gemm_fp16_kernel<<<ggrid, 256, GEMM_SMEM>>>(af, Wf + 3 * WN, out, MROWS, EMB, EMB);
}